// round 1
// baseline (speedup 1.0000x reference)
#include <cuda_runtime.h>
#include <cstdint>

// Problem constants (fixed by the reference):
//   B=8, H=8, L=1024, D=64, K=49 (num buckets)
//   x:  (B,H,L,D) fp32        = d_in[0]
//   W:  (H,D,K)   fp32        = d_in[1]
//   rp: (L,L)     int32       = d_in[2]
//   out:(B,H,L,L) fp32
#define BB 8
#define HH 8
#define LL 1024
#define DD 64
#define KK 49
#define BH (BB*HH)

// Scratch for lt = einsum('bhld,hdk->bhlk'): 64*1024*49 floats = 12.8 MB
__device__ float g_lt[BH * LL * KK];

// ---------------------------------------------------------------------------
// Kernel 1: batched small GEMM  lt[bh,i,k] = sum_d x[bh,i,d] * W[h,d,k]
// grid: (L/ROWS, BH), block: 256
// ---------------------------------------------------------------------------
#define ROWS 16

__global__ __launch_bounds__(256) void compute_lt_kernel(
    const float* __restrict__ x, const float* __restrict__ W)
{
    const int bh = blockIdx.y;
    const int h  = bh & (HH - 1);
    const int i0 = blockIdx.x * ROWS;

    __shared__ float Ws[DD * KK];     // 64*49 = 3136 floats (12.5 KB)
    __shared__ float xs[ROWS * DD];   // 16*64 = 1024 floats (4 KB)

    for (int t = threadIdx.x; t < DD * KK; t += blockDim.x)
        Ws[t] = W[h * DD * KK + t];
    for (int t = threadIdx.x; t < ROWS * DD; t += blockDim.x)
        xs[t] = x[((size_t)bh * LL + i0) * DD + t];
    __syncthreads();

    for (int o = threadIdx.x; o < ROWS * KK; o += blockDim.x) {
        const int r = o / KK;
        const int k = o - r * KK;
        float s = 0.0f;
        #pragma unroll
        for (int d = 0; d < DD; d++)
            s = fmaf(xs[r * DD + d], Ws[d * KK + k], s);
        g_lt[((size_t)bh * LL + i0 + r) * KK + k] = s;
    }
}

// ---------------------------------------------------------------------------
// Kernel 2: gather  out[bh,i,j] = lt[bh,i, rp[i,j]]
// One block per row i. Stage rp row (4 KB) + 64 lt rows (12.5 KB) in shared,
// then stream 64 * 1024 floats out via float4 stores.
// grid: (L), block: 256
// ---------------------------------------------------------------------------
__global__ __launch_bounds__(256) void gather_kernel(
    const int* __restrict__ rp, float* __restrict__ out)
{
    const int i = blockIdx.x;

    __shared__ int   bs[LL];            // bucket row, 4 KB
    __shared__ float lts[BH * KK];      // 64 lt rows, 12.25 KB

    // Stage bucket row (coalesced)
    for (int t = threadIdx.x; t < LL / 4; t += blockDim.x)
        ((int4*)bs)[t] = ((const int4*)(rp + (size_t)i * LL))[t];

    // Stage lt rows for this i across all 64 bh (64 segments of 196 B)
    for (int t = threadIdx.x; t < BH * KK; t += blockDim.x) {
        const int bh = t / KK;
        const int k  = t - bh * KK;
        lts[t] = g_lt[((size_t)bh * LL + i) * KK + k];
    }
    __syncthreads();

    // Stream output: for each bh, 1024 floats = 256 float4 (one per thread)
    const int j4 = threadIdx.x;           // 0..255, covers all L/4 exactly
    const int4  bk = ((const int4*)bs)[j4];

    #pragma unroll 4
    for (int bh = 0; bh < BH; bh++) {
        const float* row = lts + bh * KK;
        float4 v;
        v.x = row[bk.x];
        v.y = row[bk.y];
        v.z = row[bk.z];
        v.w = row[bk.w];
        float4* dst = (float4*)(out + (((size_t)bh * LL) + i) * LL);
        dst[j4] = v;
    }
}

// ---------------------------------------------------------------------------
extern "C" void kernel_launch(void* const* d_in, const int* in_sizes, int n_in,
                              void* d_out, int out_size)
{
    const float* x  = (const float*)d_in[0];
    const float* W  = (const float*)d_in[1];
    const int*   rp = (const int*)d_in[2];
    float*       out = (float*)d_out;

    dim3 g1(LL / ROWS, BH);
    compute_lt_kernel<<<g1, 256>>>(x, W);
    gather_kernel<<<LL, 256>>>(rp, out);
}

// round 2
// speedup vs baseline: 1.2797x; 1.2797x over previous
#include <cuda_runtime.h>
#include <cstdint>

// Problem constants:
//   B=8, H=8, L=1024, D=64, K=49
//   x:  (B,H,L,D) fp32   = d_in[0]
//   W:  (H,D,K)   fp32   = d_in[1]
//   rp: (L,L)     int32  = d_in[2]
//   out:(B,H,L,L) fp32
#define BB 8
#define HH 8
#define LL 1024
#define DD 64
#define KK 49
#define BH (BB*HH)

// Scratch for lt = einsum('bhld,hdk->bhlk'): 64*1024*49 floats = 12.8 MB
__device__ float g_lt[(size_t)BH * LL * KK];

// ---------------------------------------------------------------------------
// Kernel 1: batched small GEMM  lt[bh,i,k] = sum_d x[bh,i,d] * W[h,d,k]
// FFMA2 (fma.rn.f32x2) version: 2 threads per row, K split 24 / 25.
// grid: (L/RPB, BH) = (8, 64), block: 256
// ---------------------------------------------------------------------------
#define RPB 128              // rows per block
#define XS_STRIDE 65         // pad: bank-conflict-free xs[row][d] reads
#define WS_STRIDE 50         // even stride -> 8B-aligned k-pairs

__global__ __launch_bounds__(256) void compute_lt_kernel(
    const float* __restrict__ x, const float* __restrict__ W)
{
    const int bh = blockIdx.y;
    const int h  = bh & (HH - 1);
    const int i0 = blockIdx.x * RPB;
    const int tid = threadIdx.x;

    __shared__ float Ws[DD * WS_STRIDE];   // 64*50*4  = 12.8 KB
    __shared__ float xs[RPB * XS_STRIDE];  // 128*65*4 = 33.3 KB

    // Stage W[h] rearranged to stride-50 rows (coalesced LDG)
    for (int t = tid; t < DD * KK; t += 256) {
        const int d = t / KK;
        const int k = t - d * KK;
        Ws[d * WS_STRIDE + k] = W[h * DD * KK + t];
    }
    // Stage x rows (float4 LDG, scalar STS into padded layout)
    {
        const float4* xsrc = (const float4*)(x + ((size_t)bh * LL + i0) * DD);
        for (int t = tid; t < RPB * (DD / 4); t += 256) {
            float4 v = xsrc[t];
            const int row = t >> 4;
            const int pos = (t & 15) << 2;
            float* dst = xs + row * XS_STRIDE + pos;
            dst[0] = v.x; dst[1] = v.y; dst[2] = v.z; dst[3] = v.w;
        }
    }
    __syncthreads();

    const int row   = tid >> 1;        // 0..127
    const int half  = tid & 1;         // 0 or 1
    const int kbase = half * 24;       // 0 or 24 (even -> aligned pairs)

    unsigned long long acc[12];
    #pragma unroll
    for (int j = 0; j < 12; j++) acc[j] = 0ull;
    float acc48 = 0.0f;

    const float* xrow = xs + row * XS_STRIDE;

    #pragma unroll 8
    for (int d = 0; d < DD; d++) {
        const float xv = xrow[d];
        unsigned long long xp;
        asm("mov.b64 %0, {%1, %1};" : "=l"(xp) : "f"(xv));
        const unsigned long long* wrow =
            (const unsigned long long*)(Ws + d * WS_STRIDE + kbase);
        #pragma unroll
        for (int j = 0; j < 12; j++)
            asm("fma.rn.f32x2 %0, %1, %2, %0;" : "+l"(acc[j]) : "l"(xp), "l"(wrow[j]));
        if (half) acc48 = fmaf(xv, Ws[d * WS_STRIDE + 48], acc48);
    }

    float* dst = g_lt + ((size_t)bh * LL + i0 + row) * KK + kbase;
    #pragma unroll
    for (int j = 0; j < 12; j++) {
        float lo, hi;
        asm("mov.b64 {%0, %1}, %2;" : "=f"(lo), "=f"(hi) : "l"(acc[j]));
        dst[2 * j]     = lo;
        dst[2 * j + 1] = hi;
    }
    if (half) dst[24] = acc48;   // k = 48
}

// ---------------------------------------------------------------------------
// Kernel 2: gather  out[bh,i,j] = lt[bh,i, rp[i,j]]
// One block per row i, 512 threads: 2 bh-halves x 256 j-quads.
// grid: (L), block: 512
// ---------------------------------------------------------------------------
__global__ __launch_bounds__(512) void gather_kernel(
    const int* __restrict__ rp, float* __restrict__ out)
{
    const int i = blockIdx.x;
    const int tid = threadIdx.x;

    __shared__ int   bs[LL];            // bucket row, 4 KB
    __shared__ float lts[BH * KK];      // 64 lt rows, 12.25 KB

    if (tid < LL / 4)
        ((int4*)bs)[tid] = ((const int4*)(rp + (size_t)i * LL))[tid];

    for (int t = tid; t < BH * KK; t += 512) {
        const int bh = t / KK;
        const int k  = t - bh * KK;
        lts[t] = g_lt[((size_t)bh * LL + i) * KK + k];
    }
    __syncthreads();

    const int j4  = tid & 255;               // 0..255  (j quad)
    const int bh0 = (tid >> 8) * (BH / 2);   // 0 or 32
    const int4 bk = ((const int4*)bs)[j4];

    #pragma unroll 4
    for (int bh = bh0; bh < bh0 + BH / 2; bh++) {
        const float* row = lts + bh * KK;
        float4 v;
        v.x = row[bk.x];
        v.y = row[bk.y];
        v.z = row[bk.z];
        v.w = row[bk.w];
        float4* dstp = (float4*)(out + (((size_t)bh * LL) + i) * LL);
        dstp[j4] = v;
    }
}

// ---------------------------------------------------------------------------
extern "C" void kernel_launch(void* const* d_in, const int* in_sizes, int n_in,
                              void* d_out, int out_size)
{
    const float* x  = (const float*)d_in[0];
    const float* W  = (const float*)d_in[1];
    const int*   rp = (const int*)d_in[2];
    float*       out = (float*)d_out;

    dim3 g1(LL / RPB, BH);
    compute_lt_kernel<<<g1, 256>>>(x, W);
    gather_kernel<<<LL, 512>>>(rp, out);
}

// round 3
// speedup vs baseline: 1.5339x; 1.1987x over previous
#include <cuda_runtime.h>
#include <cstdint>

// Problem constants:
//   B=8, H=8, L=1024, D=64, K=49
//   x:  (B,H,L,D) fp32   = d_in[0]
//   W:  (H,D,K)   fp32   = d_in[1]
//   rp: (L,L)     int32  = d_in[2]
//   out:(B,H,L,L) fp32
#define BB 8
#define HH 8
#define LL 1024
#define DD 64
#define KK 49
#define BH (BB*HH)

// lt transposed: ltT[i][bh][k], 1024*64*49 floats = 12.8 MB
// Gather block i then reads ONE contiguous 12.5 KB segment.
__device__ float g_ltT[(size_t)LL * BH * KK];

// ---------------------------------------------------------------------------
// Kernel 1: lt[bh,i,k] = sum_d x[bh,i,d] * W[h,d,k], written as ltT[i][bh][k]
// 128 threads, 1 row per thread, all 49 k in registers (24 FFMA2 + 1 FFMA / d).
// W pairs come from smem with warp-uniform (broadcast) LDS.64.
// x read directly via LDG.128 (16 per thread, 8-d register chunks).
// Results staged in smem, then warp-cooperative contiguous copy to g_ltT.
// grid: (L/128, BH) = (8, 64), block: 128
// ---------------------------------------------------------------------------
#define RPB 128
#define WS_STRIDE 50         // even stride -> 8B-aligned k-pairs

__global__ __launch_bounds__(128) void compute_lt_kernel(
    const float* __restrict__ x, const float* __restrict__ W)
{
    const int bh  = blockIdx.y;
    const int h   = bh & (HH - 1);
    const int i0  = blockIdx.x * RPB;
    const int tid = threadIdx.x;

    __shared__ float Ws[DD * WS_STRIDE];   // 12.8 KB
    __shared__ float res[RPB * KK];        // 128*49 = 25 KB

    // Stage W[h] with stride-50 rows (coalesced LDG, aligned pairs)
    for (int t = tid; t < DD * KK; t += 128) {
        const int d = t / KK;
        const int k = t - d * KK;
        Ws[d * WS_STRIDE + k] = W[(size_t)h * DD * KK + t];
    }
    __syncthreads();

    const int row = tid;                   // 0..127
    const float4* xrow4 = (const float4*)(x + ((size_t)bh * LL + i0 + row) * DD);

    unsigned long long acc[24];
    #pragma unroll
    for (int j = 0; j < 24; j++) acc[j] = 0ull;
    float acc48 = 0.0f;

    // 8 chunks of 8 d-values; x kept in registers (2 float4 per chunk)
    for (int dc = 0; dc < 8; dc++) {
        const float4 a0 = xrow4[dc * 2];
        const float4 a1 = xrow4[dc * 2 + 1];
        float xv[8] = {a0.x, a0.y, a0.z, a0.w, a1.x, a1.y, a1.z, a1.w};
        #pragma unroll
        for (int dd = 0; dd < 8; dd++) {
            const int d = dc * 8 + dd;
            unsigned long long xp;
            asm("mov.b64 %0, {%1, %1};" : "=l"(xp) : "f"(xv[dd]));
            const unsigned long long* wrow =
                (const unsigned long long*)(Ws + d * WS_STRIDE);
            #pragma unroll
            for (int j = 0; j < 24; j++)
                asm("fma.rn.f32x2 %0, %1, %2, %0;"
                    : "+l"(acc[j]) : "l"(xp), "l"(wrow[j]));
            acc48 = fmaf(xv[dd], Ws[d * WS_STRIDE + 48], acc48);
        }
    }

    // Stage results: res[row*49 + k]. Row stride 49 (odd) -> conflict-free STS.
    {
        float* r = res + row * KK;
        #pragma unroll
        for (int j = 0; j < 24; j++) {
            float lo, hi;
            asm("mov.b64 {%0, %1}, %2;" : "=f"(lo), "=f"(hi) : "l"(acc[j]));
            r[2 * j]     = lo;
            r[2 * j + 1] = hi;
        }
        r[48] = acc48;
    }
    __syncthreads();

    // Cooperative copy out: each warp handles 32 rows; per row, 49 contiguous
    // floats -> ltT[(i0+r)*64 + bh][*]  (coalesced 196 B segments).
    const int w    = tid >> 5;             // warp 0..3
    const int lane = tid & 31;
    for (int n = 0; n < 32; n++) {
        const int r = w * 32 + n;
        const float* src = res + r * KK;
        float* dst = g_ltT + ((size_t)(i0 + r) * BH + bh) * KK;
        dst[lane] = src[lane];
        if (lane < KK - 32) dst[lane + 32] = src[lane + 32];
    }
}

// ---------------------------------------------------------------------------
// Kernel 2: gather  out[bh,i,j] = ltT[i][bh][rp[i,j]]
// One block per row i, 256 threads; lt segment is one contiguous 12.5 KB read.
// grid: (L), block: 256  -> 8 blocks/SM, single wave.
// ---------------------------------------------------------------------------
__global__ __launch_bounds__(256) void gather_kernel(
    const int* __restrict__ rp, float* __restrict__ out)
{
    const int i   = blockIdx.x;
    const int tid = threadIdx.x;

    __shared__ int   bs[LL];            // 4 KB
    __shared__ float lts[BH * KK];      // 3136 floats = 12.25 KB

    // Stage bucket row (256 int4, fully coalesced)
    ((int4*)bs)[tid] = ((const int4*)(rp + (size_t)i * LL))[tid];

    // Stage lt segment: contiguous 784 float4
    {
        const float4* src = (const float4*)(g_ltT + (size_t)i * BH * KK);
        #pragma unroll
        for (int t = tid; t < (BH * KK) / 4; t += 256)
            ((float4*)lts)[t] = src[t];
    }
    __syncthreads();

    const int4 bk = ((const int4*)bs)[tid];

    #pragma unroll 4
    for (int bh = 0; bh < BH; bh++) {
        const float* row = lts + bh * KK;
        float4 v;
        v.x = row[bk.x];
        v.y = row[bk.y];
        v.z = row[bk.z];
        v.w = row[bk.w];
        float4* dstp = (float4*)(out + (((size_t)bh * LL) + i) * LL);
        dstp[tid] = v;
    }
}

// ---------------------------------------------------------------------------
extern "C" void kernel_launch(void* const* d_in, const int* in_sizes, int n_in,
                              void* d_out, int out_size)
{
    const float* x  = (const float*)d_in[0];
    const float* W  = (const float*)d_in[1];
    const int*   rp = (const int*)d_in[2];
    float*       out = (float*)d_out;

    dim3 g1(LL / RPB, BH);
    compute_lt_kernel<<<g1, 128>>>(x, W);
    gather_kernel<<<LL, 256>>>(rp, out);
}